// round 2
// baseline (speedup 1.0000x reference)
#include <cuda_runtime.h>
#include <cstdint>
#include <cstddef>

#define B_    8
#define CIN_  64
#define COUT_ 64
#define HW_   256
#define MID_  64
#define NP_   4
#define NL_   5
#define CHUNK 4
#define TW    32

// Scratch: per-batch materialized conv weights and biases (no cudaMalloc allowed)
__device__ float g_w[B_ * COUT_ * CIN_ * 9];   // [b][cout][cin][ky][kx]
__device__ float g_b[B_ * COUT_];              // [b][cout]

// ---------------------------------------------------------------------------
// Kernel 1: hypernetwork embed.
// grid = (8 cin-groups, 8 batches), 256 threads.
// w1[b, cin*64+m] = b_wp + b_wi + h[b]@W_wp^T + index@W_wi^T
// w2[b, cin, jj]  = b_we[jj] + sum_m w1[cin,m] * W_we[jj, m]   (jj = cout*9+kk)
// g_w[b, cout, cin, kk] = conv_weight[cout,cin,kk] + w2
// g_b[b, cout] = conv_bias + h@W_bp^T + index@W_bi^T (+zero biases)
// ---------------------------------------------------------------------------
__global__ void embed_kernel(
    const float* __restrict__ h,   const float* __restrict__ index,
    const float* __restrict__ conv_weight, const float* __restrict__ conv_bias,
    const float* __restrict__ W_wp, const float* __restrict__ b_wp,
    const float* __restrict__ W_wi, const float* __restrict__ b_wi,
    const float* __restrict__ W_we, const float* __restrict__ b_we,
    const float* __restrict__ W_bp, const float* __restrict__ b_bp,
    const float* __restrict__ W_bi, const float* __restrict__ b_bi)
{
    const int g = blockIdx.x;       // cin group: cins [g*8, g*8+8)
    const int b = blockIdx.y;
    const int tid = threadIdx.x;

    __shared__ float hs[NP_];
    __shared__ float is_[NL_];
    __shared__ float w1[8 * MID_];  // w1 rows for this cin group

    if (tid < NP_) hs[tid] = h[b * NP_ + tid];
    if (tid < NL_) is_[tid] = index[tid];
    __syncthreads();

    for (int il = tid; il < 8 * MID_; il += blockDim.x) {
        int i = g * 8 * MID_ + il;                  // global row in [0, 4096)
        float v = b_wp[i] + b_wi[i];
        #pragma unroll
        for (int p = 0; p < NP_; p++) v += hs[p] * W_wp[i * NP_ + p];
        #pragma unroll
        for (int l = 0; l < NL_; l++) v += is_[l] * W_wi[i * NL_ + l];
        w1[il] = v;
    }
    __syncthreads();

    for (int e = tid; e < 8 * 576; e += blockDim.x) {
        int cl = e / 576;
        int jj = e - cl * 576;                      // cout*9 + kk
        int cin = g * 8 + cl;
        float s = b_we[jj];
        const float* wr  = &W_we[jj * MID_];
        const float* w1r = &w1[cl * MID_];
        #pragma unroll 8
        for (int m = 0; m < MID_; m++) s += w1r[m] * wr[m];
        int cout = jj / 9;
        int kk   = jj - cout * 9;
        int idx  = (cout * CIN_ + cin) * 9 + kk;
        g_w[b * COUT_ * CIN_ * 9 + idx] = conv_weight[idx] + s;
    }

    if (g == 0 && tid < COUT_) {
        float v = conv_bias[tid] + b_bp[tid] + b_bi[tid];
        #pragma unroll
        for (int p = 0; p < NP_; p++) v += hs[p] * W_bp[tid * NP_ + p];
        #pragma unroll
        for (int l = 0; l < NL_; l++) v += is_[l] * W_bi[tid * NL_ + l];
        g_b[b * COUT_ + tid] = v;
    }
}

// ---------------------------------------------------------------------------
// Packed f32x2 helpers (sm_103a): one fma-pipe op = 2 fp32 FMAs per lane.
// ---------------------------------------------------------------------------
__device__ __forceinline__ uint64_t bcast2(float v) {
    uint64_t r;
    asm("mov.b64 %0, {%1, %1};" : "=l"(r) : "f"(v));
    return r;
}
__device__ __forceinline__ void ffma2(uint64_t& d, uint64_t a, uint64_t b) {
    asm("fma.rn.f32x2 %0, %1, %2, %0;" : "+l"(d) : "l"(a), "l"(b));
}
__device__ __forceinline__ float2 unpack2(uint64_t v) {
    float2 f;
    asm("mov.b64 {%0, %1}, %2;" : "=f"(f.x), "=f"(f.y) : "l"(v));
    return f;
}

// ---------------------------------------------------------------------------
// Kernel 2: per-sample-weights 3x3 conv (stride 1, pad 1).
// grid = (8 x-tiles, 8 y-tiles, B*4 z) ; z = b*4 + cout_group (16 couts each).
// 256 threads: 16x16 layout, each thread computes a 2x2 pixel micro-tile for
// 16 couts packed as 8 f32x2 cout pairs (weight pair via broadcast LDS.64).
// ---------------------------------------------------------------------------
__global__ __launch_bounds__(256, 2)
void conv_kernel(const float* __restrict__ x, float* __restrict__ out)
{
    __shared__ float in_s[CHUNK][34][36];  // halo tile, +2 col pad vs 34 for banks
    __shared__ float w_s[CHUNK][9][16];    // [cin][k][cout] -> cout contiguous

    const int tid = threadIdx.x;
    const int tx = tid & 15;
    const int ty = tid >> 4;
    const int x0 = blockIdx.x * TW;
    const int y0 = blockIdx.y * TW;
    const int zb = blockIdx.z;
    const int b = zb >> 2;
    const int cout0 = (zb & 3) * 16;

    const float* xb = x + ((size_t)(b * CIN_) << 16);

    uint64_t acc[8][4];                    // [cout-pair][dy*2+dx]
    #pragma unroll
    for (int cp = 0; cp < 8; cp++)
        #pragma unroll
        for (int q = 0; q < 4; q++) acc[cp][q] = 0ull;

    const int lx = tx * 2;
    const int ly = ty * 2;

    for (int ch = 0; ch < CIN_ / CHUNK; ch++) {
        __syncthreads();
        // stage input halo tiles for CHUNK cins
        for (int e = tid; e < CHUNK * 34 * 34; e += 256) {
            int ci  = e / 1156;
            int rem = e - ci * 1156;
            int r   = rem / 34;
            int c   = rem - r * 34;
            int gy = y0 - 1 + r;
            int gx = x0 - 1 + c;
            float v = 0.f;
            if ((unsigned)gy < 256u && (unsigned)gx < 256u)
                v = xb[((ch * CHUNK + ci) << 16) | (gy << 8) | gx];
            in_s[ci][r][c] = v;
        }
        // stage weights for CHUNK cins x 16 couts x 9 taps
        for (int e = tid; e < CHUNK * 9 * 16; e += 256) {
            int co = e & 15;
            int t  = e >> 4;
            int ci = t / 9;
            int k  = t - ci * 9;
            w_s[ci][k][co] =
                g_w[((b * COUT_ + cout0 + co) * CIN_ + ch * CHUNK + ci) * 9 + k];
        }
        __syncthreads();

        #pragma unroll
        for (int ci = 0; ci < CHUNK; ci++) {
            #pragma unroll
            for (int ky = 0; ky < 3; ky++) {
                uint64_t ip0[4], ip1[4];
                #pragma unroll
                for (int j = 0; j < 4; j++) {
                    ip0[j] = bcast2(in_s[ci][ly + ky][lx + j]);
                    ip1[j] = bcast2(in_s[ci][ly + ky + 1][lx + j]);
                }
                #pragma unroll
                for (int kx = 0; kx < 3; kx++) {
                    #pragma unroll
                    for (int cp = 0; cp < 8; cp++) {
                        uint64_t w2 =
                            *(const uint64_t*)&w_s[ci][ky * 3 + kx][cp * 2];
                        ffma2(acc[cp][0], ip0[kx + 0], w2);
                        ffma2(acc[cp][1], ip0[kx + 1], w2);
                        ffma2(acc[cp][2], ip1[kx + 0], w2);
                        ffma2(acc[cp][3], ip1[kx + 1], w2);
                    }
                }
            }
        }
    }

    // epilogue: add bias, repack so stores are (px, px+1) contiguous float2
    #pragma unroll
    for (int cp = 0; cp < 8; cp++) {
        int c0 = cout0 + cp * 2;
        float b0 = g_b[b * COUT_ + c0];
        float b1 = g_b[b * COUT_ + c0 + 1];
        #pragma unroll
        for (int dy = 0; dy < 2; dy++) {
            float2 pa = unpack2(acc[cp][dy * 2 + 0]);  // (c0, px), (c0+1, px)
            float2 pb = unpack2(acc[cp][dy * 2 + 1]);  // (c0, px+1), (c0+1, px+1)
            int py = y0 + ly + dy;
            int px = x0 + lx;
            float2 o0 = make_float2(pa.x + b0, pb.x + b0);
            float2 o1 = make_float2(pa.y + b1, pb.y + b1);
            *(float2*)&out[(((size_t)(b * COUT_ + c0)) << 16) + (py << 8) + px] = o0;
            *(float2*)&out[(((size_t)(b * COUT_ + c0 + 1)) << 16) + (py << 8) + px] = o1;
        }
    }
}

// ---------------------------------------------------------------------------
// kernel_launch — inputs in metadata order:
// x, h, index, conv_weight, conv_bias, W_wp, b_wp, W_wi, b_wi, W_we, b_we,
// W_bp, b_bp, W_bi, b_bi
// ---------------------------------------------------------------------------
extern "C" void kernel_launch(void* const* d_in, const int* in_sizes, int n_in,
                              void* d_out, int out_size)
{
    const float* x           = (const float*)d_in[0];
    const float* h           = (const float*)d_in[1];
    const float* index       = (const float*)d_in[2];
    const float* conv_weight = (const float*)d_in[3];
    const float* conv_bias   = (const float*)d_in[4];
    const float* W_wp        = (const float*)d_in[5];
    const float* b_wp        = (const float*)d_in[6];
    const float* W_wi        = (const float*)d_in[7];
    const float* b_wi        = (const float*)d_in[8];
    const float* W_we        = (const float*)d_in[9];
    const float* b_we        = (const float*)d_in[10];
    const float* W_bp        = (const float*)d_in[11];
    const float* b_bp        = (const float*)d_in[12];
    const float* W_bi        = (const float*)d_in[13];
    const float* b_bi        = (const float*)d_in[14];
    float* out = (float*)d_out;

    dim3 g1(8, 8);
    embed_kernel<<<g1, 256>>>(h, index, conv_weight, conv_bias,
                              W_wp, b_wp, W_wi, b_wi, W_we, b_we,
                              W_bp, b_bp, W_bi, b_bi);

    dim3 g2(8, 8, B_ * 4);
    conv_kernel<<<g2, 256>>>(x, out);
}